// round 1
// baseline (speedup 1.0000x reference)
#include <cuda_runtime.h>
#include <cuda_bf16.h>
#include <math.h>
#include <math_constants.h>

#define L_DIM 2048
#define S_DIM 2048
#define B_DIM 2
#define E_DIM 1024
#define H_DIM 16
#define HD    64
#define M_ROWS (L_DIM * B_DIM)   // 4096 rows for projections

// ---------------- scratch (allocation-free: __device__ globals) ----------------
__device__ float g_Q[(size_t)B_DIM * H_DIM * L_DIM * HD];   // 16 MB
__device__ float g_K[(size_t)B_DIM * H_DIM * S_DIM * HD];   // 16 MB
__device__ float g_V[(size_t)B_DIM * H_DIM * S_DIM * HD];   // 16 MB
__device__ float g_O[(size_t)L_DIM * B_DIM * E_DIM];        // 16 MB

// ============================================================================
// Projection GEMM: C[m][n] = sum_k A[m][k] * W[n][k] + bias[n]
//   A: M x K row-major, W: N x K row-major (so this is X @ W^T + b)
// LAYOUT 0: out[m*N + n]                          (final output projection)
// LAYOUT 1: out[((b*H + h)*Lseq + l)*HD + d]      (QKV, m = l*B + b, n = h*HD + d)
// ROPE 1: apply rotary embedding over head-dim pairs in the epilogue
// ============================================================================
template<int LAYOUT, int ROPE>
__global__ void __launch_bounds__(256)
proj_gemm(const float* __restrict__ A,
          const float* __restrict__ W,
          const float* __restrict__ bias,
          float* __restrict__ out,
          int M, int N, int K)
{
    const int BK = 16;
    __shared__ float As[BK][132];   // transposed: As[k][m]
    __shared__ float Bs[BK][132];   // transposed: Bs[k][n]

    const int tid = threadIdx.x;
    const int tx  = tid & 15;       // 0..15 -> 8 output cols each
    const int ty  = tid >> 4;       // 0..15 -> 8 output rows each
    const int m0  = blockIdx.y * 128;
    const int n0  = blockIdx.x * 128;

    float acc[8][8];
#pragma unroll
    for (int i = 0; i < 8; i++)
#pragma unroll
        for (int j = 0; j < 8; j++) acc[i][j] = 0.0f;

    for (int k0 = 0; k0 < K; k0 += BK) {
        // load 128x16 tiles of A and W, transposing into smem
#pragma unroll
        for (int it = 0; it < 2; it++) {
            int id  = it * 256 + tid;      // 0..511 float4 slots
            int row = id >> 2;             // 0..127
            int kq  = (id & 3) * 4;        // 0,4,8,12
            float4 va = *(const float4*)(A + (size_t)(m0 + row) * K + k0 + kq);
            As[kq + 0][row] = va.x; As[kq + 1][row] = va.y;
            As[kq + 2][row] = va.z; As[kq + 3][row] = va.w;
            float4 vb = *(const float4*)(W + (size_t)(n0 + row) * K + k0 + kq);
            Bs[kq + 0][row] = vb.x; Bs[kq + 1][row] = vb.y;
            Bs[kq + 2][row] = vb.z; Bs[kq + 3][row] = vb.w;
        }
        __syncthreads();

#pragma unroll
        for (int k = 0; k < BK; k++) {
            float4 a0 = *(const float4*)&As[k][ty * 8];
            float4 a1 = *(const float4*)&As[k][ty * 8 + 4];
            float4 b0 = *(const float4*)&Bs[k][tx * 8];
            float4 b1 = *(const float4*)&Bs[k][tx * 8 + 4];
            float a[8] = {a0.x, a0.y, a0.z, a0.w, a1.x, a1.y, a1.z, a1.w};
            float b[8] = {b0.x, b0.y, b0.z, b0.w, b1.x, b1.y, b1.z, b1.w};
#pragma unroll
            for (int i = 0; i < 8; i++)
#pragma unroll
                for (int j = 0; j < 8; j++)
                    acc[i][j] = fmaf(a[i], b[j], acc[i][j]);
        }
        __syncthreads();
    }

    // bias
    {
        float bv[8];
#pragma unroll
        for (int j = 0; j < 8; j++) bv[j] = bias[n0 + tx * 8 + j];
#pragma unroll
        for (int i = 0; i < 8; i++)
#pragma unroll
            for (int j = 0; j < 8; j++) acc[i][j] += bv[j];
    }

    const int Lseq = M / B_DIM;

#pragma unroll
    for (int i = 0; i < 8; i++) {
        int m = m0 + ty * 8 + i;
        if (ROPE || LAYOUT == 1) {
            int l = m / B_DIM;
            int b = m - l * B_DIM;
            if (ROPE) {
#pragma unroll
                for (int p = 0; p < 4; p++) {
                    int n = n0 + tx * 8 + 2 * p;
                    int d = n & (HD - 1);        // even index within head
                    float freq = powf(10000.0f, -(float)d / (float)HD);
                    float ang  = (float)l * freq;
                    float sv, cv;
                    sincosf(ang, &sv, &cv);
                    float x1 = acc[i][2 * p];
                    float x2 = acc[i][2 * p + 1];
                    acc[i][2 * p]     = x1 * cv - x2 * sv;
                    acc[i][2 * p + 1] = x1 * sv + x2 * cv;
                }
            }
            if (LAYOUT == 1) {
                int n = n0 + tx * 8;
                int h = n / HD;
                int d = n & (HD - 1);
                float* dst = out + (((size_t)b * H_DIM + h) * Lseq + l) * HD + d;
                float4 v0 = {acc[i][0], acc[i][1], acc[i][2], acc[i][3]};
                float4 v1 = {acc[i][4], acc[i][5], acc[i][6], acc[i][7]};
                *(float4*)dst       = v0;
                *(float4*)(dst + 4) = v1;
                continue;
            }
        }
        // LAYOUT 0
        float* dst = out + (size_t)m * N + n0 + tx * 8;
        float4 v0 = {acc[i][0], acc[i][1], acc[i][2], acc[i][3]};
        float4 v1 = {acc[i][4], acc[i][5], acc[i][6], acc[i][7]};
        *(float4*)dst       = v0;
        *(float4*)(dst + 4) = v1;
    }
}

// ============================================================================
// Flash attention (fp32): per (b*H+h, 128-row Q tile), stream S in 64-chunks.
//   Qs : [d][r]  64 x 132  (d-major, transposed)
//   KP : [d][c]  64 x 132  for K, reused as P^T [c][r] after softmax
//   Vs : [s][d]  64 x 68
// Thread (ty,tx): rows r = ty*8..+7 ; score cols c = tx*4..+3 ; O cols d = tx*4..+3
// ============================================================================
#define ATTN_SMEM_FLOATS (2 * 64 * 132 + 64 * 68)

__global__ void __launch_bounds__(256)
flash_attn(const float* __restrict__ Qg,
           const float* __restrict__ Kg,
           const float* __restrict__ Vg,
           const unsigned char* __restrict__ mask,
           float* __restrict__ Og)
{
    extern __shared__ float sm[];
    float (*Qs)[132] = (float(*)[132])sm;
    float (*KP)[132] = (float(*)[132])(sm + 64 * 132);
    float (*Vs)[68]  = (float(*)[68])(sm + 2 * 64 * 132);

    const int tid = threadIdx.x;
    const int tx  = tid & 15;
    const int ty  = tid >> 4;
    const int bh  = blockIdx.y;            // b*H + h
    const int b   = bh / H_DIM;
    const int h   = bh - b * H_DIM;
    const int l0  = blockIdx.x * 128;

    const float* Qp = Qg + (size_t)bh * L_DIM * HD;
    const float* Kp = Kg + (size_t)bh * S_DIM * HD;
    const float* Vp = Vg + (size_t)bh * S_DIM * HD;

    // load Q tile (128 x 64) transposed into Qs[d][r]
#pragma unroll
    for (int it = 0; it < 8; it++) {
        int id  = it * 256 + tid;      // 0..2047 float4 slots
        int row = id >> 4;             // 0..127
        int dq  = (id & 15) * 4;       // 0..60
        float4 v = *(const float4*)(Qp + (size_t)(l0 + row) * HD + dq);
        Qs[dq + 0][row] = v.x; Qs[dq + 1][row] = v.y;
        Qs[dq + 2][row] = v.z; Qs[dq + 3][row] = v.w;
    }

    float o[8][4];
    float mi[8], li[8];
#pragma unroll
    for (int i = 0; i < 8; i++) {
        mi[i] = -CUDART_INF_F;
        li[i] = 0.0f;
#pragma unroll
        for (int j = 0; j < 4; j++) o[i][j] = 0.0f;
    }

    const float scale = 0.125f;   // 1/sqrt(64)

    for (int s0 = 0; s0 < S_DIM; s0 += 64) {
        // load K chunk transposed -> KP[d][c], V chunk natural -> Vs[s][d]
#pragma unroll
        for (int it = 0; it < 4; it++) {
            int id  = it * 256 + tid;   // 0..1023 float4 slots
            int row = id >> 4;          // 0..63
            int dq  = (id & 15) * 4;
            float4 kv = *(const float4*)(Kp + (size_t)(s0 + row) * HD + dq);
            KP[dq + 0][row] = kv.x; KP[dq + 1][row] = kv.y;
            KP[dq + 2][row] = kv.z; KP[dq + 3][row] = kv.w;
            float4 vv = *(const float4*)(Vp + (size_t)(s0 + row) * HD + dq);
            *(float4*)&Vs[row][dq] = vv;
        }
        // padding mask for this thread's 4 score columns
        bool msk[4];
#pragma unroll
        for (int j = 0; j < 4; j++)
            msk[j] = mask[(size_t)b * S_DIM + s0 + tx * 4 + j] != 0;

        __syncthreads();

        // ---- GEMM1: scores = Q @ K^T  (128 x 64) ----
        float sa[8][4];
#pragma unroll
        for (int i = 0; i < 8; i++)
#pragma unroll
            for (int j = 0; j < 4; j++) sa[i][j] = 0.0f;

#pragma unroll 4
        for (int d = 0; d < HD; d++) {
            float4 a0 = *(const float4*)&Qs[d][ty * 8];
            float4 a1 = *(const float4*)&Qs[d][ty * 8 + 4];
            float4 kk = *(const float4*)&KP[d][tx * 4];
            float a[8] = {a0.x, a0.y, a0.z, a0.w, a1.x, a1.y, a1.z, a1.w};
            float kb[4] = {kk.x, kk.y, kk.z, kk.w};
#pragma unroll
            for (int i = 0; i < 8; i++)
#pragma unroll
                for (int j = 0; j < 4; j++)
                    sa[i][j] = fmaf(a[i], kb[j], sa[i][j]);
        }
        __syncthreads();   // all reads of KP (K) done before P overwrites it

        // ---- online softmax + write P^T into KP ----
#pragma unroll
        for (int i = 0; i < 8; i++) {
            float mloc = -CUDART_INF_F;
#pragma unroll
            for (int j = 0; j < 4; j++) {
                float v = msk[j] ? -CUDART_INF_F : sa[i][j] * scale;
                sa[i][j] = v;
                mloc = fmaxf(mloc, v);
            }
#pragma unroll
            for (int off = 8; off >= 1; off >>= 1)
                mloc = fmaxf(mloc, __shfl_xor_sync(0xffffffffu, mloc, off));
            float mnew  = fmaxf(mi[i], mloc);
            float alpha = __expf(mi[i] - mnew);
            float psum  = 0.0f;
#pragma unroll
            for (int j = 0; j < 4; j++) {
                float p = __expf(sa[i][j] - mnew);
                sa[i][j] = p;
                psum += p;
            }
#pragma unroll
            for (int off = 8; off >= 1; off >>= 1)
                psum += __shfl_xor_sync(0xffffffffu, psum, off);
            li[i] = li[i] * alpha + psum;
            mi[i] = mnew;
#pragma unroll
            for (int j = 0; j < 4; j++) o[i][j] *= alpha;
#pragma unroll
            for (int j = 0; j < 4; j++)
                KP[tx * 4 + j][ty * 8 + i] = sa[i][j];
        }
        __syncthreads();   // P^T fully written

        // ---- GEMM2: O += P @ V  (128 x 64) ----
#pragma unroll 4
        for (int s = 0; s < 64; s++) {
            float4 p0 = *(const float4*)&KP[s][ty * 8];
            float4 p1 = *(const float4*)&KP[s][ty * 8 + 4];
            float4 vv = *(const float4*)&Vs[s][tx * 4];
            float p[8] = {p0.x, p0.y, p0.z, p0.w, p1.x, p1.y, p1.z, p1.w};
            float vb[4] = {vv.x, vv.y, vv.z, vv.w};
#pragma unroll
            for (int i = 0; i < 8; i++)
#pragma unroll
                for (int j = 0; j < 4; j++)
                    o[i][j] = fmaf(p[i], vb[j], o[i][j]);
        }
        __syncthreads();   // done with KP/Vs before next chunk load
    }

    // epilogue: normalize and write to (L, B, E) layout
#pragma unroll
    for (int i = 0; i < 8; i++) {
        int l = l0 + ty * 8 + i;
        float inv = 1.0f / li[i];
        float4 res = {o[i][0] * inv, o[i][1] * inv, o[i][2] * inv, o[i][3] * inv};
        *(float4*)(Og + ((size_t)l * B_DIM + b) * E_DIM + h * HD + tx * 4) = res;
    }
}

// ============================================================================
// launch
// ============================================================================
extern "C" void kernel_launch(void* const* d_in, const int* in_sizes, int n_in,
                              void* d_out, int out_size)
{
    const float* query = (const float*)d_in[0];
    const float* key   = (const float*)d_in[1];
    const float* value = (const float*)d_in[2];
    const unsigned char* mask = (const unsigned char*)d_in[3];
    const float* Wq = (const float*)d_in[4];
    const float* bq = (const float*)d_in[5];
    const float* Wk = (const float*)d_in[6];
    const float* bk = (const float*)d_in[7];
    const float* Wv = (const float*)d_in[8];
    const float* bv = (const float*)d_in[9];
    const float* Wo = (const float*)d_in[10];
    const float* bo = (const float*)d_in[11];
    float* out = (float*)d_out;

    float *Qd, *Kd, *Vd, *Od;
    cudaGetSymbolAddress((void**)&Qd, g_Q);
    cudaGetSymbolAddress((void**)&Kd, g_K);
    cudaGetSymbolAddress((void**)&Vd, g_V);
    cudaGetSymbolAddress((void**)&Od, g_O);

    const size_t attn_smem = (size_t)ATTN_SMEM_FLOATS * sizeof(float);
    cudaFuncSetAttribute(flash_attn, cudaFuncAttributeMaxDynamicSharedMemorySize,
                         (int)attn_smem);

    dim3 pgrid(E_DIM / 128, M_ROWS / 128);   // (8, 32)
    dim3 pblk(256);

    // Q/K/V projections (+RoPE for Q,K), writing [B][H][T][hd]
    proj_gemm<1, 1><<<pgrid, pblk>>>(query, Wq, bq, Qd, M_ROWS, E_DIM, E_DIM);
    proj_gemm<1, 1><<<pgrid, pblk>>>(key,   Wk, bk, Kd, M_ROWS, E_DIM, E_DIM);
    proj_gemm<1, 0><<<pgrid, pblk>>>(value, Wv, bv, Vd, M_ROWS, E_DIM, E_DIM);

    // attention
    dim3 agrid(L_DIM / 128, B_DIM * H_DIM);  // (16, 32)
    flash_attn<<<agrid, dim3(256), attn_smem>>>(Qd, Kd, Vd, mask, Od);

    // output projection -> d_out (L, B, E): row m = l*B+b matches layout 0
    proj_gemm<0, 0><<<pgrid, pblk>>>(Od, Wo, bo, out, M_ROWS, E_DIM, E_DIM);
}